// round 4
// baseline (speedup 1.0000x reference)
#include <cuda_runtime.h>
#include <math.h>
#include <float.h>

#define D        256
#define BM       32
#define BN       128
#define DK       64
#define NSPLIT   4
#define THREADS  128
#define KS_STRIDE 68    // DK + 4 pad
#define QS_STRIDE 260   // D + 4 pad
#define PS_STRIDE 132   // BN + 4 pad
#define MAXB     4096

// Scratch for split-K partials (no allocations allowed -> device globals)
__device__ float g_Opart[(size_t)NSPLIT * MAXB * D];   // unnormalized partial O
__device__ float g_m[NSPLIT * MAXB];
__device__ float g_l[NSPLIT * MAXB];

extern "C" __global__ void __launch_bounds__(THREADS)
attn_kernel(const float* __restrict__ Qg, const float* __restrict__ Kn,
            const float* __restrict__ Vn, const float* __restrict__ Kc,
            const float* __restrict__ Vc, const int* __restrict__ old_ptr,
            int Bq)
{
    extern __shared__ float smf[];
    float* Qs   = smf;                       // BM x QS_STRIDE
    float* Ks   = Qs + BM * QS_STRIDE;       // BN x KS_STRIDE
    float* Ps   = Ks + BN * KS_STRIDE;       // BM x PS_STRIDE
    float* m_sm = Ps + BM * PS_STRIDE;       // BM
    float* l_sm = m_sm + BM;                 // BM
    float* osc  = l_sm + BM;                 // BM

    const int t    = threadIdx.x;
    const int lane = t & 31;
    const int w    = t >> 5;       // warp id, owns query rows w*8 .. w*8+7
    const int sq   = t >> 4;       // S-phase row group (rows sq*4 .. +3)
    const int sk   = t & 15;       // S-phase key lane

    const int old = *old_ptr;
    const int nsz = old + Bq;
    const int q0  = blockIdx.x * BM;
    const int split = blockIdx.y;

    // key range for this split, tile-aligned
    int chunk = ((nsz + NSPLIT * BN - 1) / (NSPLIT * BN)) * BN;
    int kbeg  = split * chunk;
    int kend  = min(kbeg + chunk, nsz);

    // ---- load Q tile (pre-scaled by 1/sqrt(D)) ----
    const float qscale = 1.0f / sqrtf((float)D);   // exact 1/16 for D=256
    for (int i = t; i < BM * (D / 4); i += THREADS) {
        int r  = i / (D / 4);
        int c4 = (i % (D / 4)) * 4;
        float4 v = make_float4(0.f, 0.f, 0.f, 0.f);
        if (q0 + r < Bq)
            v = *(const float4*)(Qg + (size_t)(q0 + r) * D + c4);
        float* dst = Qs + r * QS_STRIDE + c4;
        dst[0] = v.x * qscale; dst[1] = v.y * qscale;
        dst[2] = v.z * qscale; dst[3] = v.w * qscale;
    }
    if (t < BM) { m_sm[t] = -FLT_MAX; l_sm[t] = 0.f; osc[t] = 1.f; }

    // O accumulators: 8 rows x 8 dims (vd = lane*8 .. +7)
    float4 Oa[8], Ob[8];
    #pragma unroll
    for (int i = 0; i < 8; i++) {
        Oa[i] = make_float4(0.f, 0.f, 0.f, 0.f);
        Ob[i] = make_float4(0.f, 0.f, 0.f, 0.f);
    }

    for (int kb = kbeg; kb < kend; kb += BN) {
        // ================= S = Q * K^T =================
        float s[4][8];
        #pragma unroll
        for (int i = 0; i < 4; i++)
            #pragma unroll
            for (int j = 0; j < 8; j++) s[i][j] = 0.f;

        for (int c = 0; c < D / DK; c++) {
            const int d0 = c * DK;
            __syncthreads();
            // stage K[kb..kb+BN)[d0..d0+DK) -> Ks  (coalesced LDG.128)
            #pragma unroll
            for (int p = 0; p < 16; p++) {
                int key = (t >> 4) + p * 8;
                int col = (t & 15) * 4;
                int kg  = kb + key;
                float4 v = make_float4(0.f, 0.f, 0.f, 0.f);
                if (kg < nsz) {
                    const float* src = (kg < old) ? (Kc + (size_t)kg * D)
                                                  : (Kn + (size_t)(kg - old) * D);
                    v = *(const float4*)(src + d0 + col);
                }
                *(float4*)(Ks + key * KS_STRIDE + col) = v;
            }
            __syncthreads();

            #pragma unroll 2
            for (int dd = 0; dd < DK; dd += 4) {
                float4 qv[4], kv[8];
                #pragma unroll
                for (int i = 0; i < 4; i++)
                    qv[i] = *(float4*)(Qs + (sq * 4 + i) * QS_STRIDE + d0 + dd);
                #pragma unroll
                for (int j = 0; j < 8; j++)
                    kv[j] = *(float4*)(Ks + (sk + 16 * j) * KS_STRIDE + dd);
                #pragma unroll
                for (int i = 0; i < 4; i++)
                    #pragma unroll
                    for (int j = 0; j < 8; j++)
                        s[i][j] += qv[i].x * kv[j].x + qv[i].y * kv[j].y
                                 + qv[i].z * kv[j].z + qv[i].w * kv[j].w;
            }
        }

        // ================= online softmax (per warp, half-warp reduce) =================
        #pragma unroll
        for (int i = 0; i < 4; i++) {
            const int R  = sq * 4 + i;
            const int qg = q0 + R;
            float lm = -FLT_MAX;
            #pragma unroll
            for (int j = 0; j < 8; j++) {
                int kg = kb + sk + 16 * j;
                bool ok = (kg <= old + qg) && (kg < nsz);
                s[i][j] = ok ? s[i][j] : -FLT_MAX;
                lm = fmaxf(lm, s[i][j]);
            }
            #pragma unroll
            for (int x = 1; x < 16; x <<= 1)
                lm = fmaxf(lm, __shfl_xor_sync(0xffffffffu, lm, x));
            float mo = m_sm[R];
            float mn = fmaxf(mo, lm);
            float rs = 0.f;
            #pragma unroll
            for (int j = 0; j < 8; j++) {
                float p = (s[i][j] > -FLT_MAX) ? __expf(s[i][j] - mn) : 0.f;
                s[i][j] = p;
                rs += p;
            }
            #pragma unroll
            for (int x = 1; x < 16; x <<= 1)
                rs += __shfl_xor_sync(0xffffffffu, rs, x);
            if (sk == 0) {
                float sc = __expf(mo - mn);   // 0 on first tile, 1 if tile masked
                l_sm[R] = l_sm[R] * sc + rs;
                m_sm[R] = mn;
                osc[R]  = sc;
            }
            #pragma unroll
            for (int j = 0; j < 8; j++)
                Ps[R * PS_STRIDE + sk + 16 * j] = s[i][j];
        }
        __syncwarp();

        // ================= O = O*scale + P * V =================
        #pragma unroll
        for (int i = 0; i < 8; i++) {
            float sc = osc[w * 8 + i];
            Oa[i].x *= sc; Oa[i].y *= sc; Oa[i].z *= sc; Oa[i].w *= sc;
            Ob[i].x *= sc; Ob[i].y *= sc; Ob[i].z *= sc; Ob[i].w *= sc;
        }
        #pragma unroll 2
        for (int kk = 0; kk < BN; kk++) {
            int kg = kb + kk;
            if (kg >= nsz) break;                 // uniform across CTA
            const float* vr = (kg < old) ? (Vc + (size_t)kg * D)
                                         : (Vn + (size_t)(kg - old) * D);
            float4 va = *(const float4*)(vr + lane * 8);
            float4 vb = *(const float4*)(vr + lane * 8 + 4);
            #pragma unroll
            for (int i = 0; i < 8; i++) {
                float p = Ps[(w * 8 + i) * PS_STRIDE + kk];
                Oa[i].x += p * va.x; Oa[i].y += p * va.y;
                Oa[i].z += p * va.z; Oa[i].w += p * va.w;
                Ob[i].x += p * vb.x; Ob[i].y += p * vb.y;
                Ob[i].z += p * vb.z; Ob[i].w += p * vb.w;
            }
        }
    }

    __syncthreads();
    // ---- write split partials ----
    size_t base = ((size_t)split * MAXB + q0) * D;
    #pragma unroll
    for (int i = 0; i < 8; i++) {
        int r = w * 8 + i;
        if (q0 + r < Bq) {
            float* dst = g_Opart + base + (size_t)r * D + lane * 8;
            *(float4*)dst       = Oa[i];
            *(float4*)(dst + 4) = Ob[i];
        }
    }
    if (t < BM && q0 + t < Bq) {
        g_m[split * MAXB + q0 + t] = m_sm[t];
        g_l[split * MAXB + q0 + t] = l_sm[t];
    }
}

extern "C" __global__ void combine_kernel(float* __restrict__ out, int Bq)
{
    int idx = blockIdx.x * blockDim.x + threadIdx.x;
    if (idx >= Bq * D) return;
    int q  = idx / D;
    int vd = idx - q * D;

    float M = -FLT_MAX;
    #pragma unroll
    for (int s = 0; s < NSPLIT; s++)
        M = fmaxf(M, g_m[s * MAXB + q]);

    float num = 0.f, den = 0.f;
    #pragma unroll
    for (int s = 0; s < NSPLIT; s++) {
        float wv = __expf(g_m[s * MAXB + q] - M);   // 0 for empty splits
        den += wv * g_l[s * MAXB + q];
        num += wv * g_Opart[((size_t)s * MAXB + q) * D + vd];
    }
    out[idx] = num / den;
}

extern "C" void kernel_launch(void* const* d_in, const int* in_sizes, int n_in,
                              void* d_out, int out_size)
{
    const float* q   = (const float*)d_in[0];
    const float* k   = (const float*)d_in[1];
    const float* v   = (const float*)d_in[2];
    const float* Kc  = (const float*)d_in[3];
    const float* Vc  = (const float*)d_in[4];
    const int*   oldp = (const int*)d_in[5];
    int Bq = in_sizes[0] / D;   // 2048

    size_t smem = (size_t)(BM * QS_STRIDE + BN * KS_STRIDE + BM * PS_STRIDE + 3 * BM)
                  * sizeof(float);
    cudaFuncSetAttribute((const void*)attn_kernel,
                         cudaFuncAttributeMaxDynamicSharedMemorySize, (int)smem);

    dim3 grid(Bq / BM, NSPLIT);
    attn_kernel<<<grid, THREADS, smem>>>(q, k, v, Kc, Vc, oldp, Bq);
    combine_kernel<<<(Bq * D + 255) / 256, 256>>>((float*)d_out, Bq);
}